// round 8
// baseline (speedup 1.0000x reference)
#include <cuda_runtime.h>
#include <math.h>

// Problem constants (fixed shapes from the reference)
#define HH 64
#define WW 96
#define DD 64
#define VV 4
#define CC 16
#define EPSF 1e-8f
#define DCHUNK 4

// -------- device scratch (allocation-free per harness rules) --------
__device__ float g_P[VV * 12];               // (K @ E)[:3,:] per view, row-major 3x4
__device__ float g_invK[9];                  // cur_invK[:3,:3]
__device__ float g_depth[DD];                // inverse-depth-interpolated planes
__device__ float g_srcT[VV * HH * WW * CC];  // src feats transposed to (V,H,W,C)
__device__ float g_curT[HH * WW * CC];       // cur feats transposed to (H,W,C)

// -------- fused transpose + setup --------
// Blocks 0 .. V*H-1  : transpose one (v,h) row slab of src
// Blocks V*H .. V*H+H-1 : transpose one h row slab of cur
// Block V*H+H        : setup (P = K@E rows 0..2, invK, depth planes)
__global__ void prep_kernel(const float* __restrict__ src_feats,
                            const float* __restrict__ cur_feats,
                            const float* __restrict__ src_extrinsics,
                            const float* __restrict__ src_Ks,
                            const float* __restrict__ cur_invK,
                            const float* __restrict__ min_depth,
                            const float* __restrict__ max_depth) {
    __shared__ float sh[WW * 17];  // [w][c] with pad (conflict-free)
    int b = blockIdx.x;
    int tid = threadIdx.x;  // 256 threads

    if (b == VV * HH + HH) {
        // ---- setup block ----
        if (tid < DD) {
            float inv_min = 1.0f / min_depth[0];
            float inv_max = 1.0f / max_depth[0];
            float ramp = (float)tid / (float)(DD - 1);
            g_depth[tid] = 1.0f / (inv_min + (inv_max - inv_min) * ramp);
        }
        if (tid < VV) {
            const float* K = src_Ks + tid * 16;
            const float* E = src_extrinsics + tid * 16;
            #pragma unroll
            for (int i = 0; i < 3; i++) {
                #pragma unroll
                for (int j = 0; j < 4; j++) {
                    float s = 0.0f;
                    #pragma unroll
                    for (int k = 0; k < 4; k++) s += K[i * 4 + k] * E[k * 4 + j];
                    g_P[tid * 12 + i * 4 + j] = s;
                }
            }
        }
        if (tid == 0) {
            #pragma unroll
            for (int r = 0; r < 3; r++)
                #pragma unroll
                for (int c = 0; c < 3; c++)
                    g_invK[r * 3 + c] = cur_invK[r * 4 + c];
        }
        return;
    }

    const float* in;
    float* out;
    if (b < VV * HH) {
        int v = b >> 6;          // / HH
        int h = b & (HH - 1);
        in  = src_feats + ((size_t)v * CC) * (HH * WW) + (size_t)h * WW;
        out = g_srcT + ((size_t)(v * HH + h) * WW) * CC;
    } else {
        int h = b - VV * HH;
        in  = cur_feats + (size_t)h * WW;
        out = g_curT + ((size_t)h * WW) * CC;
    }

    // load: i = c*WW + w (coalesced along w), write sh[w*17 + c]
    #pragma unroll
    for (int i = tid; i < CC * WW; i += 256) {
        int c = i / WW;
        int w = i - c * WW;
        sh[w * 17 + c] = in[(size_t)c * (HH * WW) + w];
    }
    __syncthreads();
    // store: j -> (w = j>>4, c = j&15), contiguous writes
    #pragma unroll
    for (int j = tid; j < WW * CC; j += 256) {
        int w = j >> 4;
        int c = j & 15;
        out[j] = sh[w * 17 + c];
    }
}

// -------- main cost-volume kernel: one thread per (d-chunk, h, w) --------
// DCHUNK depth planes per thread: amortizes cur-feature load + projection setup,
// and exposes DCHUNK independent gather chains per view (higher MLP).
__global__ void __launch_bounds__(128) cost_kernel(float* __restrict__ out) {
    __shared__ float sP[VV * 12];
    __shared__ float sIK[9];
    int tid = threadIdx.x;
    if (tid < VV * 12) sP[tid] = g_P[tid];
    if (tid < 9) sIK[tid] = g_invK[tid];
    __syncthreads();

    int idx = blockIdx.x * 128 + tid;   // total = H*W*(D/DCHUNK) = 98304
    int w = idx % WW;
    int t = idx / WW;
    int h = t % HH;
    int dc = t / HH;                    // 0 .. D/DCHUNK-1
    int dbase = dc * DCHUNK;

    float depth[DCHUNK];
    #pragma unroll
    for (int j = 0; j < DCHUNK; j++) depth[j] = g_depth[dbase + j];

    // ray = invK[:3,:3] @ (w+0.5, h+0.5, 1)
    float px = (float)w + 0.5f;
    float py = (float)h + 0.5f;
    float rx = sIK[0] * px + sIK[1] * py + sIK[2];
    float ry = sIK[3] * px + sIK[4] * py + sIK[5];
    float rz = sIK[6] * px + sIK[7] * py + sIK[8];

    // cur feature vector (16 ch), contiguous — loaded once per DCHUNK outputs
    const float4* curp = (const float4*)(g_curT + ((size_t)(h * WW + w) << 4));
    float4 c0 = curp[0], c1 = curp[1], c2 = curp[2], c3 = curp[3];

    float acc[DCHUNK];
    #pragma unroll
    for (int j = 0; j < DCHUNK; j++) acc[j] = 0.0f;

    #pragma unroll
    for (int v = 0; v < VV; v++) {
        const float* P = sP + v * 12;
        // q = P[:, :3] @ ray  (depth-independent part), p = P[:, 3]
        float qx = P[0] * rx + P[1] * ry + P[2]  * rz;
        float qy = P[4] * rx + P[5] * ry + P[6]  * rz;
        float qz = P[8] * rx + P[9] * ry + P[10] * rz;
        float tx = P[3], ty = P[7], tz = P[11];

        const float* srcv = g_srcT + ((size_t)v * HH * WW << 4);

        #pragma unroll
        for (int j = 0; j < DCHUNK; j++) {
            float cz = fmaf(qz, depth[j], tz);
            if (cz > 0.0f) {
                float cx = fmaf(qx, depth[j], tx);
                float cy = fmaf(qy, depth[j], ty);
                float inv = 1.0f / (cz + EPSF);
                // x = u - 0.5, y = v - 0.5 (normalize/denormalize cancels exactly)
                float x = fmaf(cx, inv, -0.5f);
                float y = fmaf(cy, inv, -0.5f);

                float x0f = floorf(x);
                float y0f = floorf(y);
                float wx1 = x - x0f, wx0 = 1.0f - wx1;
                float wy1 = y - y0f, wy0 = 1.0f - wy1;
                int x0 = (int)x0f, y0 = (int)y0f;

                bool vx0 = (x0 >= 0) && (x0 < WW);
                bool vx1 = (x0 + 1 >= 0) && (x0 + 1 < WW);
                bool vy0 = (y0 >= 0) && (y0 < HH);
                bool vy1 = (y0 + 1 >= 0) && (y0 + 1 < HH);

                float accv = 0.0f;
                #pragma unroll
                for (int dy = 0; dy < 2; dy++) {
                    bool vy = dy ? vy1 : vy0;
                    float wy = dy ? wy1 : wy0;
                    int yi = y0 + dy;
                    #pragma unroll
                    for (int dx = 0; dx < 2; dx++) {
                        bool vx = dx ? vx1 : vx0;
                        if (vy && vx) {
                            float wgt = (dx ? wx1 : wx0) * wy;
                            int xi = x0 + dx;
                            const float4* sp =
                                (const float4*)(srcv + ((size_t)(yi * WW + xi) << 4));
                            float4 s0 = sp[0], s1 = sp[1], s2 = sp[2], s3 = sp[3];
                            float dt;
                            dt  = s0.x * c0.x; dt = fmaf(s0.y, c0.y, dt);
                            dt = fmaf(s0.z, c0.z, dt); dt = fmaf(s0.w, c0.w, dt);
                            dt = fmaf(s1.x, c1.x, dt); dt = fmaf(s1.y, c1.y, dt);
                            dt = fmaf(s1.z, c1.z, dt); dt = fmaf(s1.w, c1.w, dt);
                            dt = fmaf(s2.x, c2.x, dt); dt = fmaf(s2.y, c2.y, dt);
                            dt = fmaf(s2.z, c2.z, dt); dt = fmaf(s2.w, c2.w, dt);
                            dt = fmaf(s3.x, c3.x, dt); dt = fmaf(s3.y, c3.y, dt);
                            dt = fmaf(s3.z, c3.z, dt); dt = fmaf(s3.w, c3.w, dt);
                            accv = fmaf(wgt, dt, accv);
                        }
                    }
                }
                acc[j] += accv;
            }
        }
    }

    // stores: stride H*W between depth planes, coalesced along w within warp
    #pragma unroll
    for (int j = 0; j < DCHUNK; j++)
        out[((dbase + j) * HH + h) * WW + w] = acc[j];
}

extern "C" void kernel_launch(void* const* d_in, const int* in_sizes, int n_in,
                              void* d_out, int out_size) {
    const float* cur_feats      = (const float*)d_in[0];  // (B,C,H,W)
    const float* src_feats      = (const float*)d_in[1];  // (B,V,C,H,W)
    const float* src_extrinsics = (const float*)d_in[2];  // (B,V,4,4)
    const float* src_Ks         = (const float*)d_in[3];  // (B,V,4,4)
    const float* cur_invK       = (const float*)d_in[4];  // (B,4,4)
    const float* min_depth      = (const float*)d_in[5];
    const float* max_depth      = (const float*)d_in[6];
    float* out = (float*)d_out;

    prep_kernel<<<VV * HH + HH + 1, 256>>>(src_feats, cur_feats, src_extrinsics,
                                           src_Ks, cur_invK, min_depth, max_depth);

    int total = (DD / DCHUNK) * HH * WW;   // 98304, divisible by 128
    cost_kernel<<<total / 128, 128>>>(out);
}

// round 9
// speedup vs baseline: 2.0549x; 2.0549x over previous
#include <cuda_runtime.h>
#include <cuda_fp16.h>
#include <math.h>

// Problem constants (fixed shapes from the reference)
#define HH 64
#define WW 96
#define DD 64
#define VV 4
#define CC 16
#define EPSF 1e-8f
#define DCHUNK 2

// -------- device scratch (allocation-free per harness rules) --------
__device__ float  g_P[VV * 12];               // (K @ E)[:3,:] per view, row-major 3x4
__device__ float  g_invK[9];                  // cur_invK[:3,:3]
__device__ float  g_depth[DD];                // inverse-depth-interpolated planes
__device__ __half g_srcT[VV * HH * WW * CC];  // src feats, fp16, (V,H,W,C)
__device__ float  g_curT[HH * WW * CC];       // cur feats, fp32, (H,W,C)

// -------- fused transpose + setup --------
__global__ void prep_kernel(const float* __restrict__ src_feats,
                            const float* __restrict__ cur_feats,
                            const float* __restrict__ src_extrinsics,
                            const float* __restrict__ src_Ks,
                            const float* __restrict__ cur_invK,
                            const float* __restrict__ min_depth,
                            const float* __restrict__ max_depth) {
    __shared__ float sh[WW * 17];  // [w][c] with pad (conflict-free)
    int b = blockIdx.x;
    int tid = threadIdx.x;  // 256 threads

    if (b == VV * HH + HH) {
        // ---- setup block ----
        if (tid < DD) {
            float inv_min = 1.0f / min_depth[0];
            float inv_max = 1.0f / max_depth[0];
            float ramp = (float)tid / (float)(DD - 1);
            g_depth[tid] = 1.0f / (inv_min + (inv_max - inv_min) * ramp);
        }
        if (tid < VV) {
            const float* K = src_Ks + tid * 16;
            const float* E = src_extrinsics + tid * 16;
            #pragma unroll
            for (int i = 0; i < 3; i++) {
                #pragma unroll
                for (int j = 0; j < 4; j++) {
                    float s = 0.0f;
                    #pragma unroll
                    for (int k = 0; k < 4; k++) s += K[i * 4 + k] * E[k * 4 + j];
                    g_P[tid * 12 + i * 4 + j] = s;
                }
            }
        }
        if (tid == 0) {
            #pragma unroll
            for (int r = 0; r < 3; r++)
                #pragma unroll
                for (int c = 0; c < 3; c++)
                    g_invK[r * 3 + c] = cur_invK[r * 4 + c];
        }
        return;
    }

    bool is_src = (b < VV * HH);
    const float* in;
    if (is_src) {
        int v = b >> 6;          // / HH
        int h = b & (HH - 1);
        in = src_feats + ((size_t)v * CC) * (HH * WW) + (size_t)h * WW;
    } else {
        int h = b - VV * HH;
        in = cur_feats + (size_t)h * WW;
    }

    // load: i = c*WW + w (coalesced along w), write sh[w*17 + c]
    #pragma unroll
    for (int i = tid; i < CC * WW; i += 256) {
        int c = i / WW;
        int w = i - c * WW;
        sh[w * 17 + c] = in[(size_t)c * (HH * WW) + w];
    }
    __syncthreads();
    // store: j -> (w = j>>4, c = j&15), contiguous writes
    if (is_src) {
        __half* out = g_srcT + ((size_t)b * WW << 4);   // b = v*HH+h
        #pragma unroll
        for (int j = tid; j < WW * CC; j += 256) {
            int w = j >> 4;
            int c = j & 15;
            out[j] = __float2half(sh[w * 17 + c]);
        }
    } else {
        int h = b - VV * HH;
        float* out = g_curT + ((size_t)h * WW << 4);
        #pragma unroll
        for (int j = tid; j < WW * CC; j += 256) {
            int w = j >> 4;
            int c = j & 15;
            out[j] = sh[w * 17 + c];
        }
    }
}

// 16-channel fp16 · fp32 dot (corner row = two 16B chunks = 8 half2)
__device__ __forceinline__ float dot16(float4 r0, float4 r1, const float* cf) {
    const __half2* h0 = (const __half2*)&r0;
    const __half2* h1 = (const __half2*)&r1;
    float dt = 0.0f;
    #pragma unroll
    for (int k = 0; k < 4; k++) {
        float2 f = __half22float2(h0[k]);
        dt = fmaf(f.x, cf[2 * k],     dt);
        dt = fmaf(f.y, cf[2 * k + 1], dt);
    }
    #pragma unroll
    for (int k = 0; k < 4; k++) {
        float2 f = __half22float2(h1[k]);
        dt = fmaf(f.x, cf[8 + 2 * k],     dt);
        dt = fmaf(f.y, cf[8 + 2 * k + 1], dt);
    }
    return dt;
}

// -------- main cost-volume kernel: one thread per (d-chunk, h, w) --------
__global__ void __launch_bounds__(128) cost_kernel(float* __restrict__ out) {
    __shared__ float sP[VV * 12];
    __shared__ float sIK[9];
    int tid = threadIdx.x;
    if (tid < VV * 12) sP[tid] = g_P[tid];
    if (tid < 9) sIK[tid] = g_invK[tid];
    __syncthreads();

    int idx = blockIdx.x * 128 + tid;   // total = H*W*(D/DCHUNK)
    int w = idx % WW;
    int t = idx / WW;
    int h = t % HH;
    int dc = t / HH;
    int dbase = dc * DCHUNK;

    float depth[DCHUNK];
    #pragma unroll
    for (int j = 0; j < DCHUNK; j++) depth[j] = g_depth[dbase + j];

    // ray = invK[:3,:3] @ (w+0.5, h+0.5, 1)
    float px = (float)w + 0.5f;
    float py = (float)h + 0.5f;
    float rx = sIK[0] * px + sIK[1] * py + sIK[2];
    float ry = sIK[3] * px + sIK[4] * py + sIK[5];
    float rz = sIK[6] * px + sIK[7] * py + sIK[8];

    // cur feature vector (16 ch), fp32, contiguous
    float cf[16];
    {
        const float4* curp = (const float4*)(g_curT + ((size_t)(h * WW + w) << 4));
        #pragma unroll
        for (int k = 0; k < 4; k++) {
            float4 c = curp[k];
            cf[4 * k] = c.x; cf[4 * k + 1] = c.y; cf[4 * k + 2] = c.z; cf[4 * k + 3] = c.w;
        }
    }

    float acc[DCHUNK];
    #pragma unroll
    for (int j = 0; j < DCHUNK; j++) acc[j] = 0.0f;

    #pragma unroll
    for (int v = 0; v < VV; v++) {
        const float* P = sP + v * 12;
        float qx = P[0] * rx + P[1] * ry + P[2]  * rz;
        float qy = P[4] * rx + P[5] * ry + P[6]  * rz;
        float qz = P[8] * rx + P[9] * ry + P[10] * rz;
        float tx = P[3], ty = P[7], tz = P[11];

        const __half* srcv = g_srcT + ((size_t)v * HH * WW << 4);

        #pragma unroll
        for (int j = 0; j < DCHUNK; j++) {
            float cz = fmaf(qz, depth[j], tz);
            if (cz > 0.0f) {
                float cx = fmaf(qx, depth[j], tx);
                float cy = fmaf(qy, depth[j], ty);
                float inv = 1.0f / (cz + EPSF);
                // x = u - 0.5, y = v - 0.5 (normalize/denormalize cancels exactly)
                float x = fmaf(cx, inv, -0.5f);
                float y = fmaf(cy, inv, -0.5f);

                float x0f = floorf(x);
                float y0f = floorf(y);
                float wx1 = x - x0f, wx0 = 1.0f - wx1;
                float wy1 = y - y0f, wy0 = 1.0f - wy1;
                int x0 = (int)x0f, y0 = (int)y0f;
                int x1 = x0 + 1,   y1 = y0 + 1;

                bool vx0 = (x0 >= 0) && (x0 < WW);
                bool vx1 = (x1 >= 0) && (x1 < WW);
                bool vy0 = (y0 >= 0) && (y0 < HH);
                bool vy1 = (y1 >= 0) && (y1 < HH);

                // masked weights (zero when corner invalid)
                float m00 = (vy0 && vx0) ? wy0 * wx0 : 0.0f;
                float m01 = (vy0 && vx1) ? wy0 * wx1 : 0.0f;
                float m10 = (vy1 && vx0) ? wy1 * wx0 : 0.0f;
                float m11 = (vy1 && vx1) ? wy1 * wx1 : 0.0f;

                // clamped indices — loads always in-bounds, issued unconditionally
                int x0c = min(max(x0, 0), WW - 1);
                int x1c = min(max(x1, 0), WW - 1);
                int y0c = min(max(y0, 0), HH - 1);
                int y1c = min(max(y1, 0), HH - 1);

                const float4* p00 = (const float4*)(srcv + ((size_t)(y0c * WW + x0c) << 4));
                const float4* p01 = (const float4*)(srcv + ((size_t)(y0c * WW + x1c) << 4));
                const float4* p10 = (const float4*)(srcv + ((size_t)(y1c * WW + x0c) << 4));
                const float4* p11 = (const float4*)(srcv + ((size_t)(y1c * WW + x1c) << 4));

                // 8 independent 16B loads, front-batched
                float4 a00 = p00[0], b00 = p00[1];
                float4 a01 = p01[0], b01 = p01[1];
                float4 a10 = p10[0], b10 = p10[1];
                float4 a11 = p11[0], b11 = p11[1];

                float accv;
                accv = m00 * dot16(a00, b00, cf);
                accv = fmaf(m01, dot16(a01, b01, cf), accv);
                accv = fmaf(m10, dot16(a10, b10, cf), accv);
                accv = fmaf(m11, dot16(a11, b11, cf), accv);
                acc[j] += accv;
            }
        }
    }

    #pragma unroll
    for (int j = 0; j < DCHUNK; j++)
        out[((dbase + j) * HH + h) * WW + w] = acc[j];
}

extern "C" void kernel_launch(void* const* d_in, const int* in_sizes, int n_in,
                              void* d_out, int out_size) {
    const float* cur_feats      = (const float*)d_in[0];  // (B,C,H,W)
    const float* src_feats      = (const float*)d_in[1];  // (B,V,C,H,W)
    const float* src_extrinsics = (const float*)d_in[2];  // (B,V,4,4)
    const float* src_Ks         = (const float*)d_in[3];  // (B,V,4,4)
    const float* cur_invK       = (const float*)d_in[4];  // (B,4,4)
    const float* min_depth      = (const float*)d_in[5];
    const float* max_depth      = (const float*)d_in[6];
    float* out = (float*)d_out;

    prep_kernel<<<VV * HH + HH + 1, 256>>>(src_feats, cur_feats, src_extrinsics,
                                           src_Ks, cur_invK, min_depth, max_depth);

    int total = (DD / DCHUNK) * HH * WW;   // 196608, divisible by 128
    cost_kernel<<<total / 128, 128>>>(out);
}